// round 15
// baseline (speedup 1.0000x reference)
#include <cuda_runtime.h>
#include <cuda_fp16.h>
#include <cuda.h>
#include <math.h>
#include <stdint.h>

#define BB 2
#define TT 2048
#define DD 1024
#define NHEAD 16
#define HDIM 64
#define FFN 4096
#define BT (BB*TT)
#define NGV 50000

typedef __half fp16;

// ---------------- scratch (device globals; no allocation) ----------------
__device__ float g_h[BT*DD];
__device__ float g_hn[BT*DD];
__device__ float g_value[BT*DD];
__device__ float g_kv[(size_t)BT*2048];
__device__ float2 g_rope[TT*32];
__device__ __align__(1024) fp16 g_a[BT*DD];
__device__ __align__(1024) fp16 g_s[(size_t)BT*FFN];
__device__ __align__(1024) fp16 g_e[BT*DD];
__device__ __align__(1024) fp16 g_q3[(size_t)BT*3072]; // qkv; reused as fp32 p2
#define WOFF_QKV 0
#define WOFF_WO   (3u*1024*1024)
#define WOFF_GU   (4u*1024*1024)
#define WOFF_DOWN (12u*1024*1024)
#define WOFF_KV   (16u*1024*1024)
__device__ __align__(1024) fp16 g_b[18u*1024*1024];

extern __shared__ char dynsmem[];

// ================= low-level helpers =================
__device__ __forceinline__ uint32_t smem_u32(const void* p) {
    uint32_t a;
    asm("{ .reg .u64 t; cvta.to.shared.u64 t, %1; cvt.u32.u64 %0, t; }" : "=r"(a) : "l"(p));
    return a;
}
__device__ __forceinline__ uint32_t swz128(uint32_t o) { return o ^ ((o >> 3) & 0x70); }
__device__ __forceinline__ void cp16(uint32_t s, const void* g) {
    asm volatile("cp.async.cg.shared.global [%0], [%1], 16;" :: "r"(s), "l"(g));
}
#define CP_COMMIT() asm volatile("cp.async.commit_group;")
#define CP_WAIT0()  asm volatile("cp.async.wait_group 0;")

#define MBAR_INIT(addr, cnt) \
    asm volatile("mbarrier.init.shared.b64 [%0], %1;" :: "r"((uint32_t)(addr)), "r"((uint32_t)(cnt)) : "memory")
#define MBAR_EXPECT_TX(addr, bytes) \
    asm volatile("mbarrier.arrive.expect_tx.shared.b64 _, [%0], %1;" :: "r"((uint32_t)(addr)), "r"((uint32_t)(bytes)) : "memory")
#define MBAR_WAIT(addr, parity) do { \
    uint32_t _m = (uint32_t)(addr); uint32_t _p = (uint32_t)(parity); uint32_t _d; \
    asm volatile("{\n\t.reg .pred p;\n\t" \
        "mbarrier.try_wait.parity.acquire.cta.shared::cta.b64 p, [%1], %2;\n\t" \
        "selp.b32 %0, 1, 0, p;\n\t}" : "=r"(_d) : "r"(_m), "r"(_p) : "memory"); \
    if (!_d) { \
        asm volatile("{\n\t.reg .pred P1;\n\t" \
            "WL_%=:\n\t" \
            "mbarrier.try_wait.parity.acquire.cta.shared::cta.b64 P1, [%0], %1, 0x989680;\n\t" \
            "@P1 bra.uni WD_%=;\n\t" \
            "bra.uni WL_%=;\n\t" \
            "WD_%=:\n\t}" :: "r"(_m), "r"(_p) : "memory"); \
    } \
} while (0)

#define TMA_LOAD2D(smem_addr, map_ptr, cx, cy, mbar) \
    asm volatile("cp.async.bulk.tensor.2d.shared::cta.global.tile.mbarrier::complete_tx::bytes " \
        "[%0], [%1, {%2, %3}], [%4];" \
        :: "r"((uint32_t)(smem_addr)), "l"(map_ptr), "r"((int)(cx)), "r"((int)(cy)), \
           "r"((uint32_t)(mbar)) : "memory")

__device__ __forceinline__ void ldsm4(uint32_t* r, uint32_t addr) {
    asm volatile("ldmatrix.sync.aligned.m8n8.x4.shared.b16 {%0,%1,%2,%3}, [%4];"
        : "=r"(r[0]), "=r"(r[1]), "=r"(r[2]), "=r"(r[3]) : "r"(addr));
}
__device__ __forceinline__ void ldsm4t(uint32_t* r, uint32_t addr) {
    asm volatile("ldmatrix.sync.aligned.m8n8.x4.trans.shared.b16 {%0,%1,%2,%3}, [%4];"
        : "=r"(r[0]), "=r"(r[1]), "=r"(r[2]), "=r"(r[3]) : "r"(addr));
}
__device__ __forceinline__ void mma16816(float* d, const uint32_t* a, const uint32_t* b) {
    asm volatile("mma.sync.aligned.m16n8k16.row.col.f32.f16.f16.f32 "
        "{%0,%1,%2,%3}, {%4,%5,%6,%7}, {%8,%9}, {%0,%1,%2,%3};"
        : "+f"(d[0]), "+f"(d[1]), "+f"(d[2]), "+f"(d[3])
        : "r"(a[0]), "r"(a[1]), "r"(a[2]), "r"(a[3]), "r"(b[0]), "r"(b[1]));
}
__device__ __forceinline__ uint32_t pack_h2(float x, float y) {
    __half2 h = __floats2half2_rn(x, y);
    return *(uint32_t*)&h;
}

// ================= TMA + mma.sync fp16 GEMM ====================
#define NSTG 3
#define TIL 16384
#define STG_B (2*TIL)
#define GEMM_SMEM (1024 + NSTG*STG_B)

template<int MODE>
__global__ void __launch_bounds__(256, 2) gemm_tma(
    const __grid_constant__ CUtensorMap ma,
    const __grid_constant__ CUtensorMap mb,
    float* __restrict__ C, const float* __restrict__ addC,
    const float* __restrict__ bias, const float* __restrict__ bias2,
    fp16* __restrict__ outp, const float2* __restrict__ rope,
    int M, int N, int Kloop, int kofs)
{
    const uint32_t sb = smem_u32(dynsmem);
    const uint32_t fullb = sb;
    const uint32_t stg0 = sb + 1024;
    const int tid = threadIdx.x;
    const int wid = tid >> 5, lane = tid & 31;
    const int wm = wid & 3, wn = wid >> 2;
    const int m0 = blockIdx.y * 128, n0 = blockIdx.x * 128;
    const int NT = Kloop >> 6;

    if (tid == 0) {
        #pragma unroll
        for (int s = 0; s < NSTG; s++) MBAR_INIT(fullb + 8*s, 1);
    }
    __syncthreads();
    if (tid == 0) {
        #pragma unroll
        for (int s = 0; s < 2; s++) {
            uint32_t st = stg0 + s * STG_B;
            MBAR_EXPECT_TX(fullb + 8*s, STG_B);
            TMA_LOAD2D(st,       &ma, kofs + s*64, m0, fullb + 8*s);
            TMA_LOAD2D(st + TIL, &mb, kofs + s*64, n0, fullb + 8*s);
        }
    }

    float acc[2][8][4];
    #pragma unroll
    for (int i = 0; i < 2; i++)
        #pragma unroll
        for (int j = 0; j < 8; j++)
            #pragma unroll
            for (int q = 0; q < 4; q++) acc[i][j][q] = 0.f;

    const int a_row0 = wm * 32 + (lane & 15);
    const int acbyte = (lane >> 4) * 16;
    const int b_rr = ((lane & 16) >> 1) + (lane & 7);
    const int bcbyte = (lane & 8) * 2;

    for (int kt = 0; kt < NT; kt++) {
        int s = kt % NSTG;
        MBAR_WAIT(fullb + 8*s, (kt / NSTG) & 1);
        if (tid == 0 && kt + 2 < NT) {
            int s2 = (kt + 2) % NSTG;
            uint32_t st2 = stg0 + s2 * STG_B;
            MBAR_EXPECT_TX(fullb + 8*s2, STG_B);
            TMA_LOAD2D(st2,       &ma, kofs + (kt+2)*64, m0, fullb + 8*s2);
            TMA_LOAD2D(st2 + TIL, &mb, kofs + (kt+2)*64, n0, fullb + 8*s2);
        }
        uint32_t st = stg0 + s * STG_B;
        #pragma unroll
        for (int k16 = 0; k16 < 4; k16++) {
            const int kofb = k16 * 32;
            uint32_t a0[4], a1[4];
            uint32_t oa0 = swz128((uint32_t)(a_row0 * 128 + acbyte + kofb));
            uint32_t oa1 = swz128((uint32_t)((a_row0 + 16) * 128 + acbyte + kofb));
            ldsm4(a0, st + oa0);
            ldsm4(a1, st + oa1);
            #pragma unroll
            for (int p = 0; p < 4; p++) {
                uint32_t ob = swz128((uint32_t)((wn * 64 + p * 16 + b_rr) * 128 + bcbyte + kofb));
                uint32_t bf[4];
                ldsm4(bf, st + TIL + ob);
                mma16816(acc[0][2*p],   a0, bf);
                mma16816(acc[0][2*p+1], a0, bf + 2);
                mma16816(acc[1][2*p],   a1, bf);
                mma16816(acc[1][2*p+1], a1, bf + 2);
            }
        }
        __syncthreads();
    }

    const int g = lane >> 2, t2 = (lane & 3) * 2;
    const int base_c = n0 + wn * 64;

    if (MODE == 0) {
        #pragma unroll
        for (int mt = 0; mt < 2; mt++)
            #pragma unroll
            for (int nt = 0; nt < 8; nt++) {
                int grow = m0 + wm * 32 + mt * 16 + g;
                int gcol = base_c + nt * 8 + t2;
                float2 v0 = make_float2(acc[mt][nt][0], acc[mt][nt][1]);
                float2 v1 = make_float2(acc[mt][nt][2], acc[mt][nt][3]);
                if (bias) {
                    const float* bp = (gcol < (N >> 1)) ? bias + gcol : bias2 + gcol - (N >> 1);
                    float2 bv = *(const float2*)bp;
                    v0.x += bv.x; v0.y += bv.y; v1.x += bv.x; v1.y += bv.y;
                }
                if (addC) {
                    float2 d0 = *(const float2*)(addC + (size_t)grow * N + gcol);
                    float2 d1 = *(const float2*)(addC + (size_t)(grow + 8) * N + gcol);
                    v0.x += d0.x; v0.y += d0.y; v1.x += d1.x; v1.y += d1.y;
                }
                *(float2*)(C + (size_t)grow * N + gcol) = v0;
                *(float2*)(C + (size_t)(grow + 8) * N + gcol) = v1;
            }
    } else if (MODE == 1) {
        #pragma unroll
        for (int mt = 0; mt < 2; mt++)
            #pragma unroll
            for (int rr = 0; rr < 2; rr++) {
                int row = m0 + wm * 32 + mt * 16 + g + rr * 8;
                const float2* rp = rope + (size_t)(row & (TT - 1)) * 32;
                size_t rb = (size_t)row * N;
                if (base_c < 2048) {  // q or k: rope via LUT
                    #pragma unroll
                    for (int nt = 0; nt < 4; nt++) {
                        int cc = base_c + nt * 8 + t2;
                        int d0 = cc & 63;
                        float2 cs0 = rp[d0];
                        float2 cs1 = rp[d0 + 1];
                        float vl0 = acc[mt][nt][rr*2],   vl1 = acc[mt][nt][rr*2+1];
                        float vh0 = acc[mt][nt+4][rr*2], vh1 = acc[mt][nt+4][rr*2+1];
                        float ol0 = vl0 * cs0.x - vh0 * cs0.y, oh0 = vh0 * cs0.x + vl0 * cs0.y;
                        float ol1 = vl1 * cs1.x - vh1 * cs1.y, oh1 = vh1 * cs1.x + vl1 * cs1.y;
                        *(uint32_t*)(outp + rb + cc)      = pack_h2(ol0, ol1);
                        *(uint32_t*)(outp + rb + cc + 32) = pack_h2(oh0, oh1);
                    }
                } else {  // v: plain
                    #pragma unroll
                    for (int nt = 0; nt < 8; nt++) {
                        int cc = base_c + nt * 8 + t2;
                        *(uint32_t*)(outp + rb + cc) =
                            pack_h2(acc[mt][nt][rr*2], acc[mt][nt][rr*2+1]);
                    }
                }
            }
    } else {  // MODE 2: silu(gate)*up, interleaved cols
        const int NO = N >> 1;
        #pragma unroll
        for (int mt = 0; mt < 2; mt++)
            #pragma unroll
            for (int rr = 0; rr < 2; rr++) {
                int row = m0 + wm * 32 + mt * 16 + g + rr * 8;
                size_t rb = (size_t)row * NO;
                #pragma unroll
                for (int nt = 0; nt < 8; nt++) {
                    float gg = acc[mt][nt][rr*2];
                    float uu = acc[mt][nt][rr*2+1];
                    float sv = gg / (1.f + expf(-gg)) * uu;
                    int j = (base_c + nt * 8 + t2) >> 1;
                    outp[rb + j] = __float2half_rn(sv);
                }
            }
    }
}

// ---------------- rope cos/sin LUT ----------------
__global__ void rope_lut_k(float2* __restrict__ lut) {
    int idx = blockIdx.x * 256 + threadIdx.x;
    int i = idx & 31, t = idx >> 5;
    float invf = expf(-(float)(2 * i) * (1.0f / 64.0f) * 9.2103403719761836f);
    float s, c;
    sincosf((float)t * invf, &s, &c);
    lut[idx] = make_float2(c, s);
}

// ---------------- weight convert part 1: qkv + key/val ----------------
#define D2 262144u
#define F2 1048576u
__global__ void split_w1(
    const float* __restrict__ wq, const float* __restrict__ wk,
    const float* __restrict__ wv, const float* __restrict__ kw,
    const float* __restrict__ vw, fp16* __restrict__ bh)
{
    uint32_t i = blockIdx.x * 256 + threadIdx.x;
    const float* src;
    uint32_t oo;
    if (i < 3*D2) {
        src = (i < D2) ? wq + 4*(size_t)i : (i < 2*D2) ? wk + 4*(size_t)(i - D2) : wv + 4*(size_t)(i - 2*D2);
        oo = i;
    } else if (i < 4*D2) {
        src = kw + 4*(size_t)(i - 3*D2);
        oo = (WOFF_KV >> 2) + (i - 3*D2);
    } else if (i < 5*D2) {
        src = vw + 4*(size_t)(i - 4*D2);
        oo = (WOFF_KV >> 2) + D2 + (i - 4*D2);
    } else return;
    float4 v = *(const float4*)src;
    ((uint32_t*)bh)[(size_t)oo*2]   = pack_h2(v.x, v.y);
    ((uint32_t*)bh)[(size_t)oo*2+1] = pack_h2(v.z, v.w);
}

// ---------------- weight convert part 2: wo + gate/up + down ----------------
__global__ void split_w2(
    const float* __restrict__ wo, const float* __restrict__ gw,
    const float* __restrict__ uw, const float* __restrict__ dw,
    fp16* __restrict__ bh)
{
    uint32_t i = blockIdx.x * 256 + threadIdx.x;
    const float* src;
    uint32_t oo;
    if (i < D2) {
        src = wo + 4*(size_t)i;
        oo = (WOFF_WO >> 2) + i;
    } else if (i < D2 + F2) {
        uint32_t loc = i - D2;
        uint32_t r = loc >> 8, c = loc & 255;
        src = gw + 4*(size_t)loc;
        oo = (WOFF_GU >> 2) + (2*r) * 256 + c;
    } else if (i < D2 + 2*F2) {
        uint32_t loc = i - D2 - F2;
        uint32_t r = loc >> 8, c = loc & 255;
        src = uw + 4*(size_t)loc;
        oo = (WOFF_GU >> 2) + (2*r + 1) * 256 + c;
    } else if (i < D2 + 3*F2) {
        src = dw + 4*(size_t)(i - D2 - 2*F2);
        oo = (WOFF_DOWN >> 2) + (i - D2 - 2*F2);
    } else return;
    float4 v = *(const float4*)src;
    ((uint32_t*)bh)[(size_t)oo*2]   = pack_h2(v.x, v.y);
    ((uint32_t*)bh)[(size_t)oo*2+1] = pack_h2(v.z, v.w);
}

// ---------------- RMSNorm ----------------
__global__ void rmsnorm_k(const float* __restrict__ x, const float* __restrict__ w,
                          float* __restrict__ y, fp16* __restrict__ o16) {
    int row = blockIdx.x, tid = threadIdx.x;
    float4 xv = ((const float4*)(x + (size_t)row * DD))[tid];
    float ss = xv.x*xv.x + xv.y*xv.y + xv.z*xv.z + xv.w*xv.w;
    #pragma unroll
    for (int o = 16; o; o >>= 1) ss += __shfl_xor_sync(0xffffffffu, ss, o);
    __shared__ float red[8];
    if ((tid & 31) == 0) red[tid >> 5] = ss;
    __syncthreads();
    float tot = 0.f;
    #pragma unroll
    for (int i = 0; i < 8; i++) tot += red[i];
    float inv = rsqrtf(tot * (1.0f / DD) + 1e-6f);
    float4 wv = ((const float4*)w)[tid];
    float4 r;
    r.x = xv.x * inv * wv.x; r.y = xv.y * inv * wv.y;
    r.z = xv.z * inv * wv.z; r.w = xv.w * inv * wv.w;
    if (y) ((float4*)(y + (size_t)row * DD))[tid] = r;
    size_t base = (size_t)row * DD;
    ((uint32_t*)(o16 + base))[2*tid]   = pack_h2(r.x, r.y);
    ((uint32_t*)(o16 + base))[2*tid+1] = pack_h2(r.z, r.w);
}

// ---------------- Flash attention: Q-tile 128, cp.async double-buffered --
#define FP 72
#define KVB (64*FP*2)
#define FLASH_SMEM (128*FP*2 + 4*KVB)

__global__ void __launch_bounds__(256) flash_mma(
    const fp16* __restrict__ qkv, fp16* __restrict__ o16)
{
    fp16* Qs = (fp16*)dynsmem;
    const uint32_t uQ = smem_u32(Qs);
    const uint32_t uKV = uQ + 128 * FP * 2;

    const int qt = gridDim.x - 1 - blockIdx.x;
    const int bh = blockIdx.y;
    const int bb = bh >> 4, h = bh & 15;
    const int q0 = qt * 128;
    const int tid = threadIdx.x;
    const int wid = tid >> 5, lane = tid & 31;
    const int g = lane >> 2, t2 = (lane & 3) * 2;

    const fp16* qb = qkv + ((size_t)(bb * TT + q0)) * 3072 + h * 64;
    for (int i = tid; i < 1024; i += 256) {
        int m = i >> 3, c8 = (i & 7) * 8;
        *(uint4*)&Qs[m * FP + c8] = *(const uint4*)(qb + (size_t)m * 3072 + c8);
    }

    const int NKT = 2 * qt + 2;
    {
        const fp16* kb = qkv + ((size_t)(bb * TT)) * 3072 + 1024 + h * 64;
        const fp16* vb = kb + 1024;
        for (int i = tid; i < 512; i += 256) {
            int n = i >> 3, c8 = (i & 7) * 8;
            cp16(uKV + (uint32_t)(n * FP + c8) * 2, kb + (size_t)n * 3072 + c8);
            cp16(uKV + KVB + (uint32_t)(n * FP + c8) * 2, vb + (size_t)n * 3072 + c8);
        }
        CP_COMMIT();
    }

    float m0r = -1e30f, m1r = -1e30f, l0r = 0.f, l1r = 0.f;
    float oacc[8][4];
    #pragma unroll
    for (int i = 0; i < 8; i++)
        #pragma unroll
        for (int j = 0; j < 4; j++) oacc[i][j] = 0.f;

    const int a_rb = (wid * 16 + (lane & 15)) * FP;
    const int a_cb = ((lane >> 4) << 3);
    const int b_rr = ((lane & 16) >> 1) + (lane & 7);
    const int b_cb = (lane & 8);
    const int v_rr = lane & 15;
    const int v_cb = (lane & 16) >> 1;

    for (int kt = 0; kt < NKT; kt++) {
        CP_WAIT0();
        __syncthreads();
        if (kt + 1 < NKT) {
            uint32_t dst = uKV + ((kt + 1) & 1) * 2 * KVB;
            const fp16* kb = qkv + ((size_t)(bb * TT + (kt + 1) * 64)) * 3072 + 1024 + h * 64;
            const fp16* vb = kb + 1024;
            for (int i = tid; i < 512; i += 256) {
                int n = i >> 3, c8 = (i & 7) * 8;
                cp16(dst + (uint32_t)(n * FP + c8) * 2, kb + (size_t)n * 3072 + c8);
                cp16(dst + KVB + (uint32_t)(n * FP + c8) * 2, vb + (size_t)n * 3072 + c8);
            }
            CP_COMMIT();
        }
        const uint32_t uK = uKV + (kt & 1) * 2 * KVB;
        const uint32_t uV = uK + KVB;

        float sacc[8][4];
        #pragma unroll
        for (int i = 0; i < 8; i++)
            #pragma unroll
            for (int j = 0; j < 4; j++) sacc[i][j] = 0.f;
        #pragma unroll
        for (int k16 = 0; k16 < 4; k16++) {
            const int kof = k16 * 16;
            uint32_t af[4];
            ldsm4(af, uQ + (uint32_t)(a_rb + kof + a_cb) * 2);
            uint32_t bf[4][4];
            #pragma unroll
            for (int p = 0; p < 4; p++)
                ldsm4(bf[p], uK + (uint32_t)((p * 16 + b_rr) * FP + kof + b_cb) * 2);
            #pragma unroll
            for (int nt = 0; nt < 8; nt++)
                mma16816(sacc[nt], af, &bf[nt >> 1][(nt & 1) * 2]);
        }

        const int qrow0 = q0 + wid * 16 + g;
        const int qrow1 = qrow0 + 8;
        #pragma unroll
        for (int nt = 0; nt < 8; nt++) {
            int c0 = kt * 64 + nt * 8 + t2;
            float v0 = sacc[nt][0] * 0.125f;
            float v1 = sacc[nt][1] * 0.125f;
            float v2 = sacc[nt][2] * 0.125f;
            float v3 = sacc[nt][3] * 0.125f;
            if (c0 > qrow0) v0 = -1e30f;
            if (c0 + 1 > qrow0) v1 = -1e30f;
            if (c0 > qrow1) v2 = -1e30f;
            if (c0 + 1 > qrow1) v3 = -1e30f;
            sacc[nt][0] = v0; sacc[nt][1] = v1; sacc[nt][2] = v2; sacc[nt][3] = v3;
        }
        float rm0 = -1e30f, rm1 = -1e30f;
        #pragma unroll
        for (int nt = 0; nt < 8; nt++) {
            rm0 = fmaxf(rm0, fmaxf(sacc[nt][0], sacc[nt][1]));
            rm1 = fmaxf(rm1, fmaxf(sacc[nt][2], sacc[nt][3]));
        }
        rm0 = fmaxf(rm0, __shfl_xor_sync(0xffffffffu, rm0, 1));
        rm0 = fmaxf(rm0, __shfl_xor_sync(0xffffffffu, rm0, 2));
        rm1 = fmaxf(rm1, __shfl_xor_sync(0xffffffffu, rm1, 1));
        rm1 = fmaxf(rm1, __shfl_xor_sync(0xffffffffu, rm1, 2));
        float mn0 = fmaxf(m0r, rm0), mn1 = fmaxf(m1r, rm1);
        float cor0 = __expf(m0r - mn0), cor1 = __expf(m1r - mn1);
        float sum0 = 0.f, sum1 = 0.f;
        #pragma unroll
        for (int nt = 0; nt < 8; nt++) {
            sacc[nt][0] = __expf(sacc[nt][0] - mn0);
            sacc[nt][1] = __expf(sacc[nt][1] - mn0);
            sacc[nt][2] = __expf(sacc[nt][2] - mn1);
            sacc[nt][3] = __expf(sacc[nt][3] - mn1);
            sum0 += sacc[nt][0] + sacc[nt][1];
            sum1 += sacc[nt][2] + sacc[nt][3];
        }
        sum0 += __shfl_xor_sync(0xffffffffu, sum0, 1);
        sum0 += __shfl_xor_sync(0xffffffffu, sum0, 2);
        sum1 += __shfl_xor_sync(0xffffffffu, sum1, 1);
        sum1 += __shfl_xor_sync(0xffffffffu, sum1, 2);
        l0r = l0r * cor0 + sum0; m0r = mn0;
        l1r = l1r * cor1 + sum1; m1r = mn1;
        #pragma unroll
        for (int dt = 0; dt < 8; dt++) {
            oacc[dt][0] *= cor0; oacc[dt][1] *= cor0;
            oacc[dt][2] *= cor1; oacc[dt][3] *= cor1;
        }
        #pragma unroll
        for (int j = 0; j < 4; j++) {
            uint32_t pf[4];
            pf[0] = pack_h2(sacc[2*j][0],   sacc[2*j][1]);
            pf[1] = pack_h2(sacc[2*j][2],   sacc[2*j][3]);
            pf[2] = pack_h2(sacc[2*j+1][0], sacc[2*j+1][1]);
            pf[3] = pack_h2(sacc[2*j+1][2], sacc[2*j+1][3]);
            #pragma unroll
            for (int dp = 0; dp < 4; dp++) {
                uint32_t vb4[4];
                ldsm4t(vb4, uV + (uint32_t)((16*j + v_rr) * FP + dp*16 + v_cb) * 2);
                mma16816(oacc[2*dp],   pf, &vb4[0]);
                mma16816(oacc[2*dp+1], pf, &vb4[2]);
            }
        }
    }

    float inv0 = 1.0f / l0r, inv1 = 1.0f / l1r;
    size_t ob0 = (size_t)bb * TT * DD + (size_t)(q0 + wid * 16 + g) * DD + h * HDIM;
    size_t ob1 = ob0 + 8 * DD;
    #pragma unroll
    for (int dt = 0; dt < 8; dt++) {
        *(uint32_t*)(o16 + ob0 + dt*8 + t2) = pack_h2(oacc[dt][0] * inv0, oacc[dt][1] * inv0);
        *(uint32_t*)(o16 + ob1 + dt*8 + t2) = pack_h2(oacc[dt][2] * inv1, oacc[dt][3] * inv1);
    }
}

// ---------------- engram hash + gather -> fp16 ----------------
__global__ void gather_k(const int* __restrict__ ids, const float* __restrict__ tables,
                         const int* __restrict__ hm, fp16* __restrict__ o16) {
    int tok = blockIdx.x;
    int t = tok & (TT - 1);
    int id0 = ids[tok];
    int id1 = (t >= 1) ? ids[tok - 1] : 0;
    int id2 = (t >= 2) ? ids[tok - 2] : 0;
    unsigned m0 = (unsigned)hm[0], m1 = (unsigned)hm[1], m2 = (unsigned)hm[2];
    unsigned h2 = (unsigned)id0 * m0 ^ (unsigned)id1 * m1;
    unsigned h3 = h2 ^ (unsigned)id2 * m2;
    int tid = threadIdx.x;
    size_t ob = (size_t)tok * 1024;
    #pragma unroll
    for (int r = 0; r < 4; r++) {
        int e = tid + r * 256;
        int tt = e >> 6, ee = e & 63;
        int head = tt & 7;
        unsigned hh = ((tt < 8) ? h2 : h3) + (unsigned)(head * 7919);
        int sv = (int)hh;
        int idx = sv % NGV;
        if (idx < 0) idx += NGV;
        o16[ob + e] = __float2half_rn(tables[((size_t)tt * NGV + idx) * 64 + ee]);
    }
}

// ---------------- gate ----------------
__global__ void gate_k(const float* __restrict__ hn, const float* __restrict__ kvb,
                       const float* __restrict__ nkw, const float* __restrict__ nqw,
                       float* __restrict__ value) {
    int row = blockIdx.x, tid = threadIdx.x;
    const float* keye = kvb + (size_t)row * 2048;
    const float* vale = keye + 1024;
    float4 kv = ((const float4*)keye)[tid];
    float4 hv = ((const float4*)(hn + (size_t)row * DD))[tid];
    float4 wk = ((const float4*)nkw)[tid];
    float4 wq = ((const float4*)nqw)[tid];
    float skk = kv.x*kv.x + kv.y*kv.y + kv.z*kv.z + kv.w*kv.w;
    float shh = hv.x*hv.x + hv.y*hv.y + hv.z*hv.z + hv.w*hv.w;
    float sdt = kv.x*wk.x*hv.x*wq.x + kv.y*wk.y*hv.y*wq.y
              + kv.z*wk.z*hv.z*wq.z + kv.w*wk.w*hv.w*wq.w;
    #pragma unroll
    for (int o = 16; o; o >>= 1) {
        skk += __shfl_xor_sync(0xffffffffu, skk, o);
        shh += __shfl_xor_sync(0xffffffffu, shh, o);
        sdt += __shfl_xor_sync(0xffffffffu, sdt, o);
    }
    __shared__ float r1[8], r2[8], r3[8];
    if ((tid & 31) == 0) { r1[tid>>5] = skk; r2[tid>>5] = shh; r3[tid>>5] = sdt; }
    __syncthreads();
    float tkk = 0, thh = 0, tdt = 0;
    #pragma unroll
    for (int i = 0; i < 8; i++) { tkk += r1[i]; thh += r2[i]; tdt += r3[i]; }
    float nk = rsqrtf(tkk * (1.0f / DD) + 1e-6f);
    float nh = rsqrtf(thh * (1.0f / DD) + 1e-6f);
    float gg = tdt * nk * nh * (1.0f / 32.0f);
    float ab = fabsf(gg);
    float rt = sqrtf(fmaxf(ab, 1e-6f));
    float sgn = (gg > 0.f) ? 1.f : ((gg < 0.f) ? -1.f : 0.f);
    float sig = 1.f / (1.f + expf(-rt * sgn));
    float4 vv = ((const float4*)vale)[tid];
    float4 r = make_float4(sig*vv.x, sig*vv.y, sig*vv.z, sig*vv.w);
    ((float4*)(value + (size_t)row * DD))[tid] = r;
}

// ---------------- final (float4): out += p2 + value + silu(conv) ----------
__global__ void final_k(const float* __restrict__ value, const float* __restrict__ p2,
                        const float* __restrict__ cw, float* __restrict__ out) {
    int i4 = blockIdx.x * 256 + threadIdx.x;   // BT*DD/4
    int d4 = (i4 << 2) & (DD - 1);
    int bt = i4 >> 8;
    int t = bt & (TT - 1);
    float4 c = make_float4(0.f, 0.f, 0.f, 0.f);
    float4 w0 = *(const float4*)(cw + (d4 + 0) * 4);
    float4 w1 = *(const float4*)(cw + (d4 + 1) * 4);
    float4 w2 = *(const float4*)(cw + (d4 + 2) * 4);
    float4 w3 = *(const float4*)(cw + (d4 + 3) * 4);
    const float* wp0 = (const float*)&w0;
    const float* wp1 = (const float*)&w1;
    const float* wp2 = (const float*)&w2;
    const float* wp3 = (const float*)&w3;
    #pragma unroll
    for (int kk = 0; kk < 4; kk++) {
        int tt = t - 3 + kk;
        if (tt >= 0) {
            float4 vv = *(const float4*)(value + (size_t)(bt - 3 + kk) * DD + d4);
            c.x += vv.x * wp0[kk];
            c.y += vv.y * wp1[kk];
            c.z += vv.z * wp2[kk];
            c.w += vv.w * wp3[kk];
        }
    }
    size_t base = (size_t)bt * DD + d4;
    float4 vv = *(const float4*)(value + base);
    float4 pp = *(const float4*)(p2 + base);
    float4 oo = *(const float4*)(out + base);
    oo.x += pp.x + vv.x + c.x / (1.f + expf(-c.x));
    oo.y += pp.y + vv.y + c.y / (1.f + expf(-c.y));
    oo.z += pp.z + vv.z + c.z / (1.f + expf(-c.z));
    oo.w += pp.w + vv.w + c.w / (1.f + expf(-c.w));
    *(float4*)(out + base) = oo;
}

// ================= host =================
typedef CUresult (*PFN_encode)(CUtensorMap*, CUtensorMapDataType, cuuint32_t, void*,
                               const cuuint64_t*, const cuuint64_t*, const cuuint32_t*,
                               const cuuint32_t*, CUtensorMapInterleave, CUtensorMapSwizzle,
                               CUtensorMapL2promotion, CUtensorMapFloatOOBfill);
static PFN_encode get_encoder() {
    static PFN_encode fn = nullptr;
    if (!fn) {
        void* p = nullptr;
        cudaDriverEntryPointQueryResult qr;
        cudaGetDriverEntryPoint("cuTensorMapEncodeTiled", &p, cudaEnableDefault, &qr);
        fn = (PFN_encode)p;
    }
    return fn;
}
static void make_map(CUtensorMap* m, void* ptr, uint64_t Kdim, uint64_t Rows) {
    cuuint64_t dims[2] = {Kdim, Rows};
    cuuint64_t strides[1] = {Kdim * 2};
    cuuint32_t box[2] = {64, 128};
    cuuint32_t es[2] = {1, 1};
    get_encoder()(m, CU_TENSOR_MAP_DATA_TYPE_FLOAT16, 2, ptr, dims, strides, box, es,
                  CU_TENSOR_MAP_INTERLEAVE_NONE, CU_TENSOR_MAP_SWIZZLE_128B,
                  CU_TENSOR_MAP_L2_PROMOTION_L2_128B, CU_TENSOR_MAP_FLOAT_OOB_FILL_NONE);
}
static float* symaddr(const void* sym) {
    void* p = nullptr;
    cudaGetSymbolAddress(&p, sym);
    return (float*)p;
}

template<int MODE>
static void run_gemm(fp16* a, fp16* b,
                     float* C, const float* addC, const float* bias, const float* bias2,
                     fp16* outp, const float2* rope, int M, int N, int Kfull, int Kloop,
                     int kofs, cudaStream_t st) {
    CUtensorMap ma, mb;
    make_map(&ma, a, Kfull, M);
    make_map(&mb, b, Kfull, N);
    dim3 grid(N / 128, M / 128);
    gemm_tma<MODE><<<grid, 256, GEMM_SMEM, st>>>(ma, mb, C, addC, bias, bias2, outp, rope,
                                                 M, N, Kloop, kofs);
}

extern "C" void kernel_launch(void* const* d_in, const int* in_sizes, int n_in,
                              void* d_out, int out_size) {
    const float* x     = (const float*)d_in[0];
    const int*   ids   = (const int*)d_in[1];
    const float* wq    = (const float*)d_in[3];
    const float* wk    = (const float*)d_in[4];
    const float* wv    = (const float*)d_in[5];
    const float* wo    = (const float*)d_in[6];
    const float* attnw = (const float*)d_in[7];
    const float* ffnw  = (const float*)d_in[8];
    const float* gatew = (const float*)d_in[9];
    const float* upw   = (const float*)d_in[10];
    const float* downw = (const float*)d_in[11];
    const float* embt  = (const float*)d_in[12];
    const float* keyw  = (const float*)d_in[13];
    const float* keyb  = (const float*)d_in[14];
    const float* valw  = (const float*)d_in[15];
    const float* valb  = (const float*)d_in[16];
    const float* normk = (const float*)d_in[17];
    const float* normq = (const float*)d_in[18];
    const float* convw = (const float*)d_in[19];
    const int*   hm    = (const int*)d_in[20];

    float* p_h   = symaddr(g_h);
    float* p_hn  = symaddr(g_hn);
    float* p_val = symaddr(g_value);
    float* p_kv  = symaddr(g_kv);
    float2* p_rope = (float2*)symaddr(g_rope);
    fp16* p_a  = (fp16*)symaddr(g_a);
    fp16* p_s  = (fp16*)symaddr(g_s);
    fp16* p_e  = (fp16*)symaddr(g_e);
    fp16* p_q3 = (fp16*)symaddr(g_q3);
    fp16* p_b  = (fp16*)symaddr(g_b);
    float* p_p2 = (float*)symaddr(g_q3);
    float* out = (float*)d_out;

    static bool init_done = false;
    static cudaStream_t s2, s3;
    static cudaEvent_t evStart, evW1, evW2, evA, evLut, evHn, evGU, evD2, evSide;
    if (!init_done) {
        cudaFuncSetAttribute(gemm_tma<0>, cudaFuncAttributeMaxDynamicSharedMemorySize, GEMM_SMEM);
        cudaFuncSetAttribute(gemm_tma<1>, cudaFuncAttributeMaxDynamicSharedMemorySize, GEMM_SMEM);
        cudaFuncSetAttribute(gemm_tma<2>, cudaFuncAttributeMaxDynamicSharedMemorySize, GEMM_SMEM);
        cudaFuncSetAttribute(flash_mma, cudaFuncAttributeMaxDynamicSharedMemorySize, FLASH_SMEM);
        cudaStreamCreateWithFlags(&s2, cudaStreamNonBlocking);
        cudaStreamCreateWithFlags(&s3, cudaStreamNonBlocking);
        cudaEventCreateWithFlags(&evStart, cudaEventDisableTiming);
        cudaEventCreateWithFlags(&evW1, cudaEventDisableTiming);
        cudaEventCreateWithFlags(&evW2, cudaEventDisableTiming);
        cudaEventCreateWithFlags(&evA, cudaEventDisableTiming);
        cudaEventCreateWithFlags(&evLut, cudaEventDisableTiming);
        cudaEventCreateWithFlags(&evHn, cudaEventDisableTiming);
        cudaEventCreateWithFlags(&evGU, cudaEventDisableTiming);
        cudaEventCreateWithFlags(&evD2, cudaEventDisableTiming);
        cudaEventCreateWithFlags(&evSide, cudaEventDisableTiming);
        init_done = true;
    }

    dim3 blk(256);
    cudaStream_t s0 = 0;

    cudaEventRecord(evStart, s0);

    // side s2: gather + attn rmsnorm
    cudaStreamWaitEvent(s2, evStart, 0);
    gather_k<<<BT, blk, 0, s2>>>(ids, embt, hm, p_e);
    rmsnorm_k<<<BT, blk, 0, s2>>>(x, attnw, nullptr, p_a);
    cudaEventRecord(evA, s2);

    // side s3: rope LUT + weight convert part 2
    cudaStreamWaitEvent(s3, evStart, 0);
    rope_lut_k<<<(TT * 32) / 256, blk, 0, s3>>>(p_rope);
    cudaEventRecord(evLut, s3);
    split_w2<<<(D2 + 3*F2 + 255) / 256, blk, 0, s3>>>(wo, gatew, upw, downw, p_b);
    cudaEventRecord(evW2, s3);

    // main: weight convert part 1
    split_w1<<<(5*D2 + 255) / 256, blk, 0, s0>>>(wq, wk, wv, keyw, valw, p_b);
    cudaEventRecord(evW1, s0);

    // side s2: kv GEMM
    cudaStreamWaitEvent(s2, evW1, 0);
    run_gemm<0>(p_e, p_b + WOFF_KV, p_kv, nullptr, keyb, valb, nullptr, nullptr,
                BT, 2048, DD, DD, 0, s2);

    // main chain
    cudaStreamWaitEvent(s0, evA, 0);
    cudaStreamWaitEvent(s0, evLut, 0);
    run_gemm<1>(p_a, p_b + WOFF_QKV, nullptr, nullptr, nullptr, nullptr, p_q3, p_rope,
                BT, 3072, DD, DD, 0, s0);
    flash_mma<<<dim3(TT / 128, BB * NHEAD), 256, FLASH_SMEM, s0>>>(p_q3, p_a);
    cudaStreamWaitEvent(s0, evW2, 0);
    run_gemm<0>(p_a, p_b + WOFF_WO, p_h, x, nullptr, nullptr, nullptr, nullptr,
                BT, DD, DD, DD, 0, s0);
    rmsnorm_k<<<BT, blk, 0, s0>>>(p_h, ffnw, p_hn, p_a);
    cudaEventRecord(evHn, s0);
    run_gemm<2>(p_a, p_b + WOFF_GU, nullptr, nullptr, nullptr, nullptr, p_s, nullptr,
                BT, 2 * FFN, DD, DD, 0, s0);
    cudaEventRecord(evGU, s0);
    run_gemm<0>(p_s, p_b + WOFF_DOWN, out, p_h, nullptr, nullptr, nullptr, nullptr,
                BT, DD, FFN, 2048, 0, s0);
    cudaStreamWaitEvent(s3, evGU, 0);
    run_gemm<0>(p_s, p_b + WOFF_DOWN, p_p2, nullptr, nullptr, nullptr, nullptr, nullptr,
                BT, DD, FFN, 2048, 2048, s3);
    cudaEventRecord(evD2, s3);

    // side s2: gate
    cudaStreamWaitEvent(s2, evHn, 0);
    gate_k<<<BT, blk, 0, s2>>>(p_hn, p_kv, normk, normq, p_val);
    cudaEventRecord(evSide, s2);

    // join + final
    cudaStreamWaitEvent(s0, evSide, 0);
    cudaStreamWaitEvent(s0, evD2, 0);
    final_k<<<(BT * DD / 4) / 256, blk, 0, s0>>>(p_val, p_p2, convw, out);
}

// round 16
// speedup vs baseline: 1.0042x; 1.0042x over previous
#include <cuda_runtime.h>
#include <cuda_fp16.h>
#include <cuda.h>
#include <math.h>
#include <stdint.h>

#define BB 2
#define TT 2048
#define DD 1024
#define NHEAD 16
#define HDIM 64
#define FFN 4096
#define BT (BB*TT)
#define NGV 50000

typedef __half fp16;

// ---------------- scratch (device globals; no allocation) ----------------
__device__ float g_h[BT*DD];
__device__ float g_hn[BT*DD];
__device__ float g_value[BT*DD];
__device__ float g_kv[(size_t)BT*2048];
__device__ float2 g_rope[TT*32];
__device__ __align__(1024) fp16 g_a[BT*DD];
__device__ __align__(1024) fp16 g_s[(size_t)BT*FFN];
__device__ __align__(1024) fp16 g_e[BT*DD];
__device__ __align__(1024) fp16 g_q3[(size_t)BT*3072]; // qkv; reused as fp32 p2
#define WOFF_QKV 0
#define WOFF_WO   (3u*1024*1024)
#define WOFF_GU   (4u*1024*1024)
#define WOFF_DOWN (12u*1024*1024)
#define WOFF_KV   (16u*1024*1024)
__device__ __align__(1024) fp16 g_b[18u*1024*1024];

extern __shared__ char dynsmem[];

// ================= low-level helpers =================
__device__ __forceinline__ uint32_t smem_u32(const void* p) {
    uint32_t a;
    asm("{ .reg .u64 t; cvta.to.shared.u64 t, %1; cvt.u32.u64 %0, t; }" : "=r"(a) : "l"(p));
    return a;
}
__device__ __forceinline__ uint32_t swz128(uint32_t o) { return o ^ ((o >> 3) & 0x70); }
__device__ __forceinline__ void cp16(uint32_t s, const void* g) {
    asm volatile("cp.async.cg.shared.global [%0], [%1], 16;" :: "r"(s), "l"(g));
}
#define CP_COMMIT() asm volatile("cp.async.commit_group;")
#define CP_WAIT0()  asm volatile("cp.async.wait_group 0;")

#define MBAR_INIT(addr, cnt) \
    asm volatile("mbarrier.init.shared.b64 [%0], %1;" :: "r"((uint32_t)(addr)), "r"((uint32_t)(cnt)) : "memory")
#define MBAR_EXPECT_TX(addr, bytes) \
    asm volatile("mbarrier.arrive.expect_tx.shared.b64 _, [%0], %1;" :: "r"((uint32_t)(addr)), "r"((uint32_t)(bytes)) : "memory")
#define MBAR_WAIT(addr, parity) do { \
    uint32_t _m = (uint32_t)(addr); uint32_t _p = (uint32_t)(parity); uint32_t _d; \
    asm volatile("{\n\t.reg .pred p;\n\t" \
        "mbarrier.try_wait.parity.acquire.cta.shared::cta.b64 p, [%1], %2;\n\t" \
        "selp.b32 %0, 1, 0, p;\n\t}" : "=r"(_d) : "r"(_m), "r"(_p) : "memory"); \
    if (!_d) { \
        asm volatile("{\n\t.reg .pred P1;\n\t" \
            "WL_%=:\n\t" \
            "mbarrier.try_wait.parity.acquire.cta.shared::cta.b64 P1, [%0], %1, 0x989680;\n\t" \
            "@P1 bra.uni WD_%=;\n\t" \
            "bra.uni WL_%=;\n\t" \
            "WD_%=:\n\t}" :: "r"(_m), "r"(_p) : "memory"); \
    } \
} while (0)

#define TMA_LOAD2D(smem_addr, map_ptr, cx, cy, mbar) \
    asm volatile("cp.async.bulk.tensor.2d.shared::cta.global.tile.mbarrier::complete_tx::bytes " \
        "[%0], [%1, {%2, %3}], [%4];" \
        :: "r"((uint32_t)(smem_addr)), "l"(map_ptr), "r"((int)(cx)), "r"((int)(cy)), \
           "r"((uint32_t)(mbar)) : "memory")

__device__ __forceinline__ void ldsm4(uint32_t* r, uint32_t addr) {
    asm volatile("ldmatrix.sync.aligned.m8n8.x4.shared.b16 {%0,%1,%2,%3}, [%4];"
        : "=r"(r[0]), "=r"(r[1]), "=r"(r[2]), "=r"(r[3]) : "r"(addr));
}
__device__ __forceinline__ void ldsm4t(uint32_t* r, uint32_t addr) {
    asm volatile("ldmatrix.sync.aligned.m8n8.x4.trans.shared.b16 {%0,%1,%2,%3}, [%4];"
        : "=r"(r[0]), "=r"(r[1]), "=r"(r[2]), "=r"(r[3]) : "r"(addr));
}
__device__ __forceinline__ void mma16816(float* d, const uint32_t* a, const uint32_t* b) {
    asm volatile("mma.sync.aligned.m16n8k16.row.col.f32.f16.f16.f32 "
        "{%0,%1,%2,%3}, {%4,%5,%6,%7}, {%8,%9}, {%0,%1,%2,%3};"
        : "+f"(d[0]), "+f"(d[1]), "+f"(d[2]), "+f"(d[3])
        : "r"(a[0]), "r"(a[1]), "r"(a[2]), "r"(a[3]), "r"(b[0]), "r"(b[1]));
}
__device__ __forceinline__ uint32_t pack_h2(float x, float y) {
    __half2 h = __floats2half2_rn(x, y);
    return *(uint32_t*)&h;
}

// ================= TMA + mma.sync fp16 GEMM ====================
#define NSTG 3
#define TIL 16384
#define STG_B (2*TIL)
#define GEMM_SMEM (1024 + NSTG*STG_B)

template<int MODE>
__global__ void __launch_bounds__(256, 2) gemm_tma(
    const __grid_constant__ CUtensorMap ma,
    const __grid_constant__ CUtensorMap mb,
    float* __restrict__ C, const float* __restrict__ addC,
    const float* __restrict__ bias, const float* __restrict__ bias2,
    fp16* __restrict__ outp, const float2* __restrict__ rope,
    int M, int N, int Kloop, int kofs)
{
    const uint32_t sb = smem_u32(dynsmem);
    const uint32_t fullb = sb;
    const uint32_t stg0 = sb + 1024;
    const int tid = threadIdx.x;
    const int wid = tid >> 5, lane = tid & 31;
    const int wm = wid & 3, wn = wid >> 2;
    const int m0 = blockIdx.y * 128, n0 = blockIdx.x * 128;
    const int NT = Kloop >> 6;

    if (tid == 0) {
        #pragma unroll
        for (int s = 0; s < NSTG; s++) MBAR_INIT(fullb + 8*s, 1);
    }
    __syncthreads();
    if (tid == 0) {
        #pragma unroll
        for (int s = 0; s < 2; s++) {
            uint32_t st = stg0 + s * STG_B;
            MBAR_EXPECT_TX(fullb + 8*s, STG_B);
            TMA_LOAD2D(st,       &ma, kofs + s*64, m0, fullb + 8*s);
            TMA_LOAD2D(st + TIL, &mb, kofs + s*64, n0, fullb + 8*s);
        }
    }

    float acc[2][8][4];
    #pragma unroll
    for (int i = 0; i < 2; i++)
        #pragma unroll
        for (int j = 0; j < 8; j++)
            #pragma unroll
            for (int q = 0; q < 4; q++) acc[i][j][q] = 0.f;

    const int a_row0 = wm * 32 + (lane & 15);
    const int acbyte = (lane >> 4) * 16;
    const int b_rr = ((lane & 16) >> 1) + (lane & 7);
    const int bcbyte = (lane & 8) * 2;

    for (int kt = 0; kt < NT; kt++) {
        int s = kt % NSTG;
        MBAR_WAIT(fullb + 8*s, (kt / NSTG) & 1);
        if (tid == 0 && kt + 2 < NT) {
            int s2 = (kt + 2) % NSTG;
            uint32_t st2 = stg0 + s2 * STG_B;
            MBAR_EXPECT_TX(fullb + 8*s2, STG_B);
            TMA_LOAD2D(st2,       &ma, kofs + (kt+2)*64, m0, fullb + 8*s2);
            TMA_LOAD2D(st2 + TIL, &mb, kofs + (kt+2)*64, n0, fullb + 8*s2);
        }
        uint32_t st = stg0 + s * STG_B;
        #pragma unroll
        for (int k16 = 0; k16 < 4; k16++) {
            const int kofb = k16 * 32;
            uint32_t a0[4], a1[4];
            uint32_t oa0 = swz128((uint32_t)(a_row0 * 128 + acbyte + kofb));
            uint32_t oa1 = swz128((uint32_t)((a_row0 + 16) * 128 + acbyte + kofb));
            ldsm4(a0, st + oa0);
            ldsm4(a1, st + oa1);
            #pragma unroll
            for (int p = 0; p < 4; p++) {
                uint32_t ob = swz128((uint32_t)((wn * 64 + p * 16 + b_rr) * 128 + bcbyte + kofb));
                uint32_t bf[4];
                ldsm4(bf, st + TIL + ob);
                mma16816(acc[0][2*p],   a0, bf);
                mma16816(acc[0][2*p+1], a0, bf + 2);
                mma16816(acc[1][2*p],   a1, bf);
                mma16816(acc[1][2*p+1], a1, bf + 2);
            }
        }
        __syncthreads();
    }

    const int g = lane >> 2, t2 = (lane & 3) * 2;
    const int base_c = n0 + wn * 64;

    if (MODE == 0) {
        #pragma unroll
        for (int mt = 0; mt < 2; mt++)
            #pragma unroll
            for (int nt = 0; nt < 8; nt++) {
                int grow = m0 + wm * 32 + mt * 16 + g;
                int gcol = base_c + nt * 8 + t2;
                float2 v0 = make_float2(acc[mt][nt][0], acc[mt][nt][1]);
                float2 v1 = make_float2(acc[mt][nt][2], acc[mt][nt][3]);
                if (bias) {
                    const float* bp = (gcol < (N >> 1)) ? bias + gcol : bias2 + gcol - (N >> 1);
                    float2 bv = *(const float2*)bp;
                    v0.x += bv.x; v0.y += bv.y; v1.x += bv.x; v1.y += bv.y;
                }
                if (addC) {
                    float2 d0 = *(const float2*)(addC + (size_t)grow * N + gcol);
                    float2 d1 = *(const float2*)(addC + (size_t)(grow + 8) * N + gcol);
                    v0.x += d0.x; v0.y += d0.y; v1.x += d1.x; v1.y += d1.y;
                }
                *(float2*)(C + (size_t)grow * N + gcol) = v0;
                *(float2*)(C + (size_t)(grow + 8) * N + gcol) = v1;
            }
    } else if (MODE == 1) {
        #pragma unroll
        for (int mt = 0; mt < 2; mt++)
            #pragma unroll
            for (int rr = 0; rr < 2; rr++) {
                int row = m0 + wm * 32 + mt * 16 + g + rr * 8;
                const float2* rp = rope + (size_t)(row & (TT - 1)) * 32;
                size_t rb = (size_t)row * N;
                if (base_c < 2048) {  // q or k: rope via LUT
                    #pragma unroll
                    for (int nt = 0; nt < 4; nt++) {
                        int cc = base_c + nt * 8 + t2;
                        int d0 = cc & 63;
                        float2 cs0 = rp[d0];
                        float2 cs1 = rp[d0 + 1];
                        float vl0 = acc[mt][nt][rr*2],   vl1 = acc[mt][nt][rr*2+1];
                        float vh0 = acc[mt][nt+4][rr*2], vh1 = acc[mt][nt+4][rr*2+1];
                        float ol0 = vl0 * cs0.x - vh0 * cs0.y, oh0 = vh0 * cs0.x + vl0 * cs0.y;
                        float ol1 = vl1 * cs1.x - vh1 * cs1.y, oh1 = vh1 * cs1.x + vl1 * cs1.y;
                        *(uint32_t*)(outp + rb + cc)      = pack_h2(ol0, ol1);
                        *(uint32_t*)(outp + rb + cc + 32) = pack_h2(oh0, oh1);
                    }
                } else {  // v: plain
                    #pragma unroll
                    for (int nt = 0; nt < 8; nt++) {
                        int cc = base_c + nt * 8 + t2;
                        *(uint32_t*)(outp + rb + cc) =
                            pack_h2(acc[mt][nt][rr*2], acc[mt][nt][rr*2+1]);
                    }
                }
            }
    } else {  // MODE 2: silu(gate)*up, interleaved cols
        const int NO = N >> 1;
        #pragma unroll
        for (int mt = 0; mt < 2; mt++)
            #pragma unroll
            for (int rr = 0; rr < 2; rr++) {
                int row = m0 + wm * 32 + mt * 16 + g + rr * 8;
                size_t rb = (size_t)row * NO;
                #pragma unroll
                for (int nt = 0; nt < 8; nt++) {
                    float gg = acc[mt][nt][rr*2];
                    float uu = acc[mt][nt][rr*2+1];
                    float sv = gg / (1.f + expf(-gg)) * uu;
                    int j = (base_c + nt * 8 + t2) >> 1;
                    outp[rb + j] = __float2half_rn(sv);
                }
            }
    }
}

// ---------------- rope cos/sin LUT ----------------
__global__ void rope_lut_k(float2* __restrict__ lut) {
    int idx = blockIdx.x * 256 + threadIdx.x;
    int i = idx & 31, t = idx >> 5;
    float invf = expf(-(float)(2 * i) * (1.0f / 64.0f) * 9.2103403719761836f);
    float s, c;
    sincosf((float)t * invf, &s, &c);
    lut[idx] = make_float2(c, s);
}

// ---------------- weight convert part 1: qkv + key/val ----------------
#define D2 262144u
#define F2 1048576u
__global__ void split_w1(
    const float* __restrict__ wq, const float* __restrict__ wk,
    const float* __restrict__ wv, const float* __restrict__ kw,
    const float* __restrict__ vw, fp16* __restrict__ bh)
{
    uint32_t i = blockIdx.x * 256 + threadIdx.x;
    const float* src;
    uint32_t oo;
    if (i < 3*D2) {
        src = (i < D2) ? wq + 4*(size_t)i : (i < 2*D2) ? wk + 4*(size_t)(i - D2) : wv + 4*(size_t)(i - 2*D2);
        oo = i;
    } else if (i < 4*D2) {
        src = kw + 4*(size_t)(i - 3*D2);
        oo = (WOFF_KV >> 2) + (i - 3*D2);
    } else if (i < 5*D2) {
        src = vw + 4*(size_t)(i - 4*D2);
        oo = (WOFF_KV >> 2) + D2 + (i - 4*D2);
    } else return;
    float4 v = *(const float4*)src;
    ((uint32_t*)bh)[(size_t)oo*2]   = pack_h2(v.x, v.y);
    ((uint32_t*)bh)[(size_t)oo*2+1] = pack_h2(v.z, v.w);
}

// ---------------- weight convert part 2: wo + gate/up + down ----------------
__global__ void split_w2(
    const float* __restrict__ wo, const float* __restrict__ gw,
    const float* __restrict__ uw, const float* __restrict__ dw,
    fp16* __restrict__ bh)
{
    uint32_t i = blockIdx.x * 256 + threadIdx.x;
    const float* src;
    uint32_t oo;
    if (i < D2) {
        src = wo + 4*(size_t)i;
        oo = (WOFF_WO >> 2) + i;
    } else if (i < D2 + F2) {
        uint32_t loc = i - D2;
        uint32_t r = loc >> 8, c = loc & 255;
        src = gw + 4*(size_t)loc;
        oo = (WOFF_GU >> 2) + (2*r) * 256 + c;
    } else if (i < D2 + 2*F2) {
        uint32_t loc = i - D2 - F2;
        uint32_t r = loc >> 8, c = loc & 255;
        src = uw + 4*(size_t)loc;
        oo = (WOFF_GU >> 2) + (2*r + 1) * 256 + c;
    } else if (i < D2 + 3*F2) {
        src = dw + 4*(size_t)(i - D2 - 2*F2);
        oo = (WOFF_DOWN >> 2) + (i - D2 - 2*F2);
    } else return;
    float4 v = *(const float4*)src;
    ((uint32_t*)bh)[(size_t)oo*2]   = pack_h2(v.x, v.y);
    ((uint32_t*)bh)[(size_t)oo*2+1] = pack_h2(v.z, v.w);
}

// ---------------- RMSNorm ----------------
__global__ void rmsnorm_k(const float* __restrict__ x, const float* __restrict__ w,
                          float* __restrict__ y, fp16* __restrict__ o16) {
    int row = blockIdx.x, tid = threadIdx.x;
    float4 xv = ((const float4*)(x + (size_t)row * DD))[tid];
    float ss = xv.x*xv.x + xv.y*xv.y + xv.z*xv.z + xv.w*xv.w;
    #pragma unroll
    for (int o = 16; o; o >>= 1) ss += __shfl_xor_sync(0xffffffffu, ss, o);
    __shared__ float red[8];
    if ((tid & 31) == 0) red[tid >> 5] = ss;
    __syncthreads();
    float tot = 0.f;
    #pragma unroll
    for (int i = 0; i < 8; i++) tot += red[i];
    float inv = rsqrtf(tot * (1.0f / DD) + 1e-6f);
    float4 wv = ((const float4*)w)[tid];
    float4 r;
    r.x = xv.x * inv * wv.x; r.y = xv.y * inv * wv.y;
    r.z = xv.z * inv * wv.z; r.w = xv.w * inv * wv.w;
    if (y) ((float4*)(y + (size_t)row * DD))[tid] = r;
    size_t base = (size_t)row * DD;
    ((uint32_t*)(o16 + base))[2*tid]   = pack_h2(r.x, r.y);
    ((uint32_t*)(o16 + base))[2*tid+1] = pack_h2(r.z, r.w);
}

// ---------------- Flash attention: Q-tile 128, cp.async double-buffered --
#define FP 72
#define KVB (64*FP*2)
#define FLASH_SMEM (128*FP*2 + 4*KVB)

__global__ void __launch_bounds__(256) flash_mma(
    const fp16* __restrict__ qkv, fp16* __restrict__ o16)
{
    fp16* Qs = (fp16*)dynsmem;
    const uint32_t uQ = smem_u32(Qs);
    const uint32_t uKV = uQ + 128 * FP * 2;

    const int qt = gridDim.x - 1 - blockIdx.x;
    const int bh = blockIdx.y;
    const int bb = bh >> 4, h = bh & 15;
    const int q0 = qt * 128;
    const int tid = threadIdx.x;
    const int wid = tid >> 5, lane = tid & 31;
    const int g = lane >> 2, t2 = (lane & 3) * 2;

    const fp16* qb = qkv + ((size_t)(bb * TT + q0)) * 3072 + h * 64;
    for (int i = tid; i < 1024; i += 256) {
        int m = i >> 3, c8 = (i & 7) * 8;
        *(uint4*)&Qs[m * FP + c8] = *(const uint4*)(qb + (size_t)m * 3072 + c8);
    }

    const int NKT = 2 * qt + 2;
    {
        const fp16* kb = qkv + ((size_t)(bb * TT)) * 3072 + 1024 + h * 64;
        const fp16* vb = kb + 1024;
        for (int i = tid; i < 512; i += 256) {
            int n = i >> 3, c8 = (i & 7) * 8;
            cp16(uKV + (uint32_t)(n * FP + c8) * 2, kb + (size_t)n * 3072 + c8);
            cp16(uKV + KVB + (uint32_t)(n * FP + c8) * 2, vb + (size_t)n * 3072 + c8);
        }
        CP_COMMIT();
    }

    float m0r = -1e30f, m1r = -1e30f, l0r = 0.f, l1r = 0.f;
    float oacc[8][4];
    #pragma unroll
    for (int i = 0; i < 8; i++)
        #pragma unroll
        for (int j = 0; j < 4; j++) oacc[i][j] = 0.f;

    const int a_rb = (wid * 16 + (lane & 15)) * FP;
    const int a_cb = ((lane >> 4) << 3);
    const int b_rr = ((lane & 16) >> 1) + (lane & 7);
    const int b_cb = (lane & 8);
    const int v_rr = lane & 15;
    const int v_cb = (lane & 16) >> 1;

    for (int kt = 0; kt < NKT; kt++) {
        CP_WAIT0();
        __syncthreads();
        if (kt + 1 < NKT) {
            uint32_t dst = uKV + ((kt + 1) & 1) * 2 * KVB;
            const fp16* kb = qkv + ((size_t)(bb * TT + (kt + 1) * 64)) * 3072 + 1024 + h * 64;
            const fp16* vb = kb + 1024;
            for (int i = tid; i < 512; i += 256) {
                int n = i >> 3, c8 = (i & 7) * 8;
                cp16(dst + (uint32_t)(n * FP + c8) * 2, kb + (size_t)n * 3072 + c8);
                cp16(dst + KVB + (uint32_t)(n * FP + c8) * 2, vb + (size_t)n * 3072 + c8);
            }
            CP_COMMIT();
        }
        const uint32_t uK = uKV + (kt & 1) * 2 * KVB;
        const uint32_t uV = uK + KVB;

        float sacc[8][4];
        #pragma unroll
        for (int i = 0; i < 8; i++)
            #pragma unroll
            for (int j = 0; j < 4; j++) sacc[i][j] = 0.f;
        #pragma unroll
        for (int k16 = 0; k16 < 4; k16++) {
            const int kof = k16 * 16;
            uint32_t af[4];
            ldsm4(af, uQ + (uint32_t)(a_rb + kof + a_cb) * 2);
            uint32_t bf[4][4];
            #pragma unroll
            for (int p = 0; p < 4; p++)
                ldsm4(bf[p], uK + (uint32_t)((p * 16 + b_rr) * FP + kof + b_cb) * 2);
            #pragma unroll
            for (int nt = 0; nt < 8; nt++)
                mma16816(sacc[nt], af, &bf[nt >> 1][(nt & 1) * 2]);
        }

        const int qrow0 = q0 + wid * 16 + g;
        const int qrow1 = qrow0 + 8;
        #pragma unroll
        for (int nt = 0; nt < 8; nt++) {
            int c0 = kt * 64 + nt * 8 + t2;
            float v0 = sacc[nt][0] * 0.125f;
            float v1 = sacc[nt][1] * 0.125f;
            float v2 = sacc[nt][2] * 0.125f;
            float v3 = sacc[nt][3] * 0.125f;
            if (c0 > qrow0) v0 = -1e30f;
            if (c0 + 1 > qrow0) v1 = -1e30f;
            if (c0 > qrow1) v2 = -1e30f;
            if (c0 + 1 > qrow1) v3 = -1e30f;
            sacc[nt][0] = v0; sacc[nt][1] = v1; sacc[nt][2] = v2; sacc[nt][3] = v3;
        }
        float rm0 = -1e30f, rm1 = -1e30f;
        #pragma unroll
        for (int nt = 0; nt < 8; nt++) {
            rm0 = fmaxf(rm0, fmaxf(sacc[nt][0], sacc[nt][1]));
            rm1 = fmaxf(rm1, fmaxf(sacc[nt][2], sacc[nt][3]));
        }
        rm0 = fmaxf(rm0, __shfl_xor_sync(0xffffffffu, rm0, 1));
        rm0 = fmaxf(rm0, __shfl_xor_sync(0xffffffffu, rm0, 2));
        rm1 = fmaxf(rm1, __shfl_xor_sync(0xffffffffu, rm1, 1));
        rm1 = fmaxf(rm1, __shfl_xor_sync(0xffffffffu, rm1, 2));
        float mn0 = fmaxf(m0r, rm0), mn1 = fmaxf(m1r, rm1);
        float cor0 = __expf(m0r - mn0), cor1 = __expf(m1r - mn1);
        float sum0 = 0.f, sum1 = 0.f;
        #pragma unroll
        for (int nt = 0; nt < 8; nt++) {
            sacc[nt][0] = __expf(sacc[nt][0] - mn0);
            sacc[nt][1] = __expf(sacc[nt][1] - mn0);
            sacc[nt][2] = __expf(sacc[nt][2] - mn1);
            sacc[nt][3] = __expf(sacc[nt][3] - mn1);
            sum0 += sacc[nt][0] + sacc[nt][1];
            sum1 += sacc[nt][2] + sacc[nt][3];
        }
        sum0 += __shfl_xor_sync(0xffffffffu, sum0, 1);
        sum0 += __shfl_xor_sync(0xffffffffu, sum0, 2);
        sum1 += __shfl_xor_sync(0xffffffffu, sum1, 1);
        sum1 += __shfl_xor_sync(0xffffffffu, sum1, 2);
        l0r = l0r * cor0 + sum0; m0r = mn0;
        l1r = l1r * cor1 + sum1; m1r = mn1;
        #pragma unroll
        for (int dt = 0; dt < 8; dt++) {
            oacc[dt][0] *= cor0; oacc[dt][1] *= cor0;
            oacc[dt][2] *= cor1; oacc[dt][3] *= cor1;
        }
        #pragma unroll
        for (int j = 0; j < 4; j++) {
            uint32_t pf[4];
            pf[0] = pack_h2(sacc[2*j][0],   sacc[2*j][1]);
            pf[1] = pack_h2(sacc[2*j][2],   sacc[2*j][3]);
            pf[2] = pack_h2(sacc[2*j+1][0], sacc[2*j+1][1]);
            pf[3] = pack_h2(sacc[2*j+1][2], sacc[2*j+1][3]);
            #pragma unroll
            for (int dp = 0; dp < 4; dp++) {
                uint32_t vb4[4];
                ldsm4t(vb4, uV + (uint32_t)((16*j + v_rr) * FP + dp*16 + v_cb) * 2);
                mma16816(oacc[2*dp],   pf, &vb4[0]);
                mma16816(oacc[2*dp+1], pf, &vb4[2]);
            }
        }
    }

    float inv0 = 1.0f / l0r, inv1 = 1.0f / l1r;
    size_t ob0 = (size_t)bb * TT * DD + (size_t)(q0 + wid * 16 + g) * DD + h * HDIM;
    size_t ob1 = ob0 + 8 * DD;
    #pragma unroll
    for (int dt = 0; dt < 8; dt++) {
        *(uint32_t*)(o16 + ob0 + dt*8 + t2) = pack_h2(oacc[dt][0] * inv0, oacc[dt][1] * inv0);
        *(uint32_t*)(o16 + ob1 + dt*8 + t2) = pack_h2(oacc[dt][2] * inv1, oacc[dt][3] * inv1);
    }
}

// ---------------- engram hash + gather -> fp16 ----------------
__global__ void gather_k(const int* __restrict__ ids, const float* __restrict__ tables,
                         const int* __restrict__ hm, fp16* __restrict__ o16) {
    int tok = blockIdx.x;
    int t = tok & (TT - 1);
    int id0 = ids[tok];
    int id1 = (t >= 1) ? ids[tok - 1] : 0;
    int id2 = (t >= 2) ? ids[tok - 2] : 0;
    unsigned m0 = (unsigned)hm[0], m1 = (unsigned)hm[1], m2 = (unsigned)hm[2];
    unsigned h2 = (unsigned)id0 * m0 ^ (unsigned)id1 * m1;
    unsigned h3 = h2 ^ (unsigned)id2 * m2;
    int tid = threadIdx.x;
    size_t ob = (size_t)tok * 1024;
    #pragma unroll
    for (int r = 0; r < 4; r++) {
        int e = tid + r * 256;
        int tt = e >> 6, ee = e & 63;
        int head = tt & 7;
        unsigned hh = ((tt < 8) ? h2 : h3) + (unsigned)(head * 7919);
        int sv = (int)hh;
        int idx = sv % NGV;
        if (idx < 0) idx += NGV;
        o16[ob + e] = __float2half_rn(tables[((size_t)tt * NGV + idx) * 64 + ee]);
    }
}

// ---------------- gate ----------------
__global__ void gate_k(const float* __restrict__ hn, const float* __restrict__ kvb,
                       const float* __restrict__ nkw, const float* __restrict__ nqw,
                       float* __restrict__ value) {
    int row = blockIdx.x, tid = threadIdx.x;
    const float* keye = kvb + (size_t)row * 2048;
    const float* vale = keye + 1024;
    float4 kv = ((const float4*)keye)[tid];
    float4 hv = ((const float4*)(hn + (size_t)row * DD))[tid];
    float4 wk = ((const float4*)nkw)[tid];
    float4 wq = ((const float4*)nqw)[tid];
    float skk = kv.x*kv.x + kv.y*kv.y + kv.z*kv.z + kv.w*kv.w;
    float shh = hv.x*hv.x + hv.y*hv.y + hv.z*hv.z + hv.w*hv.w;
    float sdt = kv.x*wk.x*hv.x*wq.x + kv.y*wk.y*hv.y*wq.y
              + kv.z*wk.z*hv.z*wq.z + kv.w*wk.w*hv.w*wq.w;
    #pragma unroll
    for (int o = 16; o; o >>= 1) {
        skk += __shfl_xor_sync(0xffffffffu, skk, o);
        shh += __shfl_xor_sync(0xffffffffu, shh, o);
        sdt += __shfl_xor_sync(0xffffffffu, sdt, o);
    }
    __shared__ float r1[8], r2[8], r3[8];
    if ((tid & 31) == 0) { r1[tid>>5] = skk; r2[tid>>5] = shh; r3[tid>>5] = sdt; }
    __syncthreads();
    float tkk = 0, thh = 0, tdt = 0;
    #pragma unroll
    for (int i = 0; i < 8; i++) { tkk += r1[i]; thh += r2[i]; tdt += r3[i]; }
    float nk = rsqrtf(tkk * (1.0f / DD) + 1e-6f);
    float nh = rsqrtf(thh * (1.0f / DD) + 1e-6f);
    float gg = tdt * nk * nh * (1.0f / 32.0f);
    float ab = fabsf(gg);
    float rt = sqrtf(fmaxf(ab, 1e-6f));
    float sgn = (gg > 0.f) ? 1.f : ((gg < 0.f) ? -1.f : 0.f);
    float sig = 1.f / (1.f + expf(-rt * sgn));
    float4 vv = ((const float4*)vale)[tid];
    float4 r = make_float4(sig*vv.x, sig*vv.y, sig*vv.z, sig*vv.w);
    ((float4*)(value + (size_t)row * DD))[tid] = r;
}

// ---------------- final (float4): out += p2 + value + silu(conv) ----------
__global__ void final_k(const float* __restrict__ value, const float* __restrict__ p2,
                        const float* __restrict__ cw, float* __restrict__ out) {
    int i4 = blockIdx.x * 256 + threadIdx.x;   // BT*DD/4
    int d4 = (i4 << 2) & (DD - 1);
    int bt = i4 >> 8;
    int t = bt & (TT - 1);
    float4 c = make_float4(0.f, 0.f, 0.f, 0.f);
    float4 w0 = *(const float4*)(cw + (d4 + 0) * 4);
    float4 w1 = *(const float4*)(cw + (d4 + 1) * 4);
    float4 w2 = *(const float4*)(cw + (d4 + 2) * 4);
    float4 w3 = *(const float4*)(cw + (d4 + 3) * 4);
    const float* wp0 = (const float*)&w0;
    const float* wp1 = (const float*)&w1;
    const float* wp2 = (const float*)&w2;
    const float* wp3 = (const float*)&w3;
    #pragma unroll
    for (int kk = 0; kk < 4; kk++) {
        int tt = t - 3 + kk;
        if (tt >= 0) {
            float4 vv = *(const float4*)(value + (size_t)(bt - 3 + kk) * DD + d4);
            c.x += vv.x * wp0[kk];
            c.y += vv.y * wp1[kk];
            c.z += vv.z * wp2[kk];
            c.w += vv.w * wp3[kk];
        }
    }
    size_t base = (size_t)bt * DD + d4;
    float4 vv = *(const float4*)(value + base);
    float4 pp = *(const float4*)(p2 + base);
    float4 oo = *(const float4*)(out + base);
    oo.x += pp.x + vv.x + c.x / (1.f + expf(-c.x));
    oo.y += pp.y + vv.y + c.y / (1.f + expf(-c.y));
    oo.z += pp.z + vv.z + c.z / (1.f + expf(-c.z));
    oo.w += pp.w + vv.w + c.w / (1.f + expf(-c.w));
    *(float4*)(out + base) = oo;
}

// ================= host =================
typedef CUresult (*PFN_encode)(CUtensorMap*, CUtensorMapDataType, cuuint32_t, void*,
                               const cuuint64_t*, const cuuint64_t*, const cuuint32_t*,
                               const cuuint32_t*, CUtensorMapInterleave, CUtensorMapSwizzle,
                               CUtensorMapL2promotion, CUtensorMapFloatOOBfill);
static PFN_encode get_encoder() {
    static PFN_encode fn = nullptr;
    if (!fn) {
        void* p = nullptr;
        cudaDriverEntryPointQueryResult qr;
        cudaGetDriverEntryPoint("cuTensorMapEncodeTiled", &p, cudaEnableDefault, &qr);
        fn = (PFN_encode)p;
    }
    return fn;
}
static void make_map(CUtensorMap* m, void* ptr, uint64_t Kdim, uint64_t Rows) {
    cuuint64_t dims[2] = {Kdim, Rows};
    cuuint64_t strides[1] = {Kdim * 2};
    cuuint32_t box[2] = {64, 128};
    cuuint32_t es[2] = {1, 1};
    get_encoder()(m, CU_TENSOR_MAP_DATA_TYPE_FLOAT16, 2, ptr, dims, strides, box, es,
                  CU_TENSOR_MAP_INTERLEAVE_NONE, CU_TENSOR_MAP_SWIZZLE_128B,
                  CU_TENSOR_MAP_L2_PROMOTION_L2_128B, CU_TENSOR_MAP_FLOAT_OOB_FILL_NONE);
}
static float* symaddr(const void* sym) {
    void* p = nullptr;
    cudaGetSymbolAddress(&p, sym);
    return (float*)p;
}

template<int MODE>
static void run_gemm(fp16* a, fp16* b,
                     float* C, const float* addC, const float* bias, const float* bias2,
                     fp16* outp, const float2* rope, int M, int N, int Kfull, int Kloop,
                     int kofs, cudaStream_t st) {
    CUtensorMap ma, mb;
    make_map(&ma, a, Kfull, M);
    make_map(&mb, b, Kfull, N);
    dim3 grid(N / 128, M / 128);
    gemm_tma<MODE><<<grid, 256, GEMM_SMEM, st>>>(ma, mb, C, addC, bias, bias2, outp, rope,
                                                 M, N, Kloop, kofs);
}

extern "C" void kernel_launch(void* const* d_in, const int* in_sizes, int n_in,
                              void* d_out, int out_size) {
    const float* x     = (const float*)d_in[0];
    const int*   ids   = (const int*)d_in[1];
    const float* wq    = (const float*)d_in[3];
    const float* wk    = (const float*)d_in[4];
    const float* wv    = (const float*)d_in[5];
    const float* wo    = (const float*)d_in[6];
    const float* attnw = (const float*)d_in[7];
    const float* ffnw  = (const float*)d_in[8];
    const float* gatew = (const float*)d_in[9];
    const float* upw   = (const float*)d_in[10];
    const float* downw = (const float*)d_in[11];
    const float* embt  = (const float*)d_in[12];
    const float* keyw  = (const float*)d_in[13];
    const float* keyb  = (const float*)d_in[14];
    const float* valw  = (const float*)d_in[15];
    const float* valb  = (const float*)d_in[16];
    const float* normk = (const float*)d_in[17];
    const float* normq = (const float*)d_in[18];
    const float* convw = (const float*)d_in[19];
    const int*   hm    = (const int*)d_in[20];

    float* p_h   = symaddr(g_h);
    float* p_hn  = symaddr(g_hn);
    float* p_val = symaddr(g_value);
    float* p_kv  = symaddr(g_kv);
    float2* p_rope = (float2*)symaddr(g_rope);
    fp16* p_a  = (fp16*)symaddr(g_a);
    fp16* p_s  = (fp16*)symaddr(g_s);
    fp16* p_e  = (fp16*)symaddr(g_e);
    fp16* p_q3 = (fp16*)symaddr(g_q3);
    fp16* p_b  = (fp16*)symaddr(g_b);
    float* p_p2 = (float*)symaddr(g_q3);
    float* out = (float*)d_out;

    static bool init_done = false;
    static cudaStream_t s2, s3;
    static cudaEvent_t evStart, evW1, evW2, evA, evLut, evG, evHn, evGU, evD2, evSide;
    if (!init_done) {
        cudaFuncSetAttribute(gemm_tma<0>, cudaFuncAttributeMaxDynamicSharedMemorySize, GEMM_SMEM);
        cudaFuncSetAttribute(gemm_tma<1>, cudaFuncAttributeMaxDynamicSharedMemorySize, GEMM_SMEM);
        cudaFuncSetAttribute(gemm_tma<2>, cudaFuncAttributeMaxDynamicSharedMemorySize, GEMM_SMEM);
        cudaFuncSetAttribute(flash_mma, cudaFuncAttributeMaxDynamicSharedMemorySize, FLASH_SMEM);
        cudaStreamCreateWithFlags(&s2, cudaStreamNonBlocking);
        cudaStreamCreateWithFlags(&s3, cudaStreamNonBlocking);
        cudaEventCreateWithFlags(&evStart, cudaEventDisableTiming);
        cudaEventCreateWithFlags(&evW1, cudaEventDisableTiming);
        cudaEventCreateWithFlags(&evW2, cudaEventDisableTiming);
        cudaEventCreateWithFlags(&evA, cudaEventDisableTiming);
        cudaEventCreateWithFlags(&evLut, cudaEventDisableTiming);
        cudaEventCreateWithFlags(&evG, cudaEventDisableTiming);
        cudaEventCreateWithFlags(&evHn, cudaEventDisableTiming);
        cudaEventCreateWithFlags(&evGU, cudaEventDisableTiming);
        cudaEventCreateWithFlags(&evD2, cudaEventDisableTiming);
        cudaEventCreateWithFlags(&evSide, cudaEventDisableTiming);
        init_done = true;
    }

    dim3 blk(256);
    cudaStream_t s0 = 0;

    cudaEventRecord(evStart, s0);

    // side s2: attn rmsnorm ONLY (critical-path input for QKV)
    cudaStreamWaitEvent(s2, evStart, 0);
    rmsnorm_k<<<BT, blk, 0, s2>>>(x, attnw, nullptr, p_a);
    cudaEventRecord(evA, s2);

    // side s3: rope LUT -> gather -> weight convert part 2 (all off critical path)
    cudaStreamWaitEvent(s3, evStart, 0);
    rope_lut_k<<<(TT * 32) / 256, blk, 0, s3>>>(p_rope);
    cudaEventRecord(evLut, s3);
    gather_k<<<BT, blk, 0, s3>>>(ids, embt, hm, p_e);
    cudaEventRecord(evG, s3);
    split_w2<<<(D2 + 3*F2 + 255) / 256, blk, 0, s3>>>(wo, gatew, upw, downw, p_b);
    cudaEventRecord(evW2, s3);

    // main: weight convert part 1 (qkv + key/val)
    split_w1<<<(5*D2 + 255) / 256, blk, 0, s0>>>(wq, wk, wv, keyw, valw, p_b);
    cudaEventRecord(evW1, s0);

    // side s2: kv GEMM (needs emb from s3 + part1 weights)
    cudaStreamWaitEvent(s2, evG, 0);
    cudaStreamWaitEvent(s2, evW1, 0);
    run_gemm<0>(p_e, p_b + WOFF_KV, p_kv, nullptr, keyb, valb, nullptr, nullptr,
                BT, 2048, DD, DD, 0, s2);

    // main chain: QKV starts as soon as rmsnorm + LUT + w1 are done (~8us)
    cudaStreamWaitEvent(s0, evA, 0);
    cudaStreamWaitEvent(s0, evLut, 0);
    run_gemm<1>(p_a, p_b + WOFF_QKV, nullptr, nullptr, nullptr, nullptr, p_q3, p_rope,
                BT, 3072, DD, DD, 0, s0);
    flash_mma<<<dim3(TT / 128, BB * NHEAD), 256, FLASH_SMEM, s0>>>(p_q3, p_a);
    cudaStreamWaitEvent(s0, evW2, 0);
    run_gemm<0>(p_a, p_b + WOFF_WO, p_h, x, nullptr, nullptr, nullptr, nullptr,
                BT, DD, DD, DD, 0, s0);
    rmsnorm_k<<<BT, blk, 0, s0>>>(p_h, ffnw, p_hn, p_a);
    cudaEventRecord(evHn, s0);
    run_gemm<2>(p_a, p_b + WOFF_GU, nullptr, nullptr, nullptr, nullptr, p_s, nullptr,
                BT, 2 * FFN, DD, DD, 0, s0);
    cudaEventRecord(evGU, s0);
    run_gemm<0>(p_s, p_b + WOFF_DOWN, out, p_h, nullptr, nullptr, nullptr, nullptr,
                BT, DD, FFN, 2048, 0, s0);
    cudaStreamWaitEvent(s3, evGU, 0);
    run_gemm<0>(p_s, p_b + WOFF_DOWN, p_p2, nullptr, nullptr, nullptr, nullptr, nullptr,
                BT, DD, FFN, 2048, 2048, s3);
    cudaEventRecord(evD2, s3);

    // side s2: gate (needs hn + kv)
    cudaStreamWaitEvent(s2, evHn, 0);
    gate_k<<<BT, blk, 0, s2>>>(p_hn, p_kv, normk, normq, p_val);
    cudaEventRecord(evSide, s2);

    // join + final
    cudaStreamWaitEvent(s0, evSide, 0);
    cudaStreamWaitEvent(s0, evD2, 0);
    final_k<<<(BT * DD / 4) / 256, blk, 0, s0>>>(p_val, p_p2, convw, out);
}